// round 2
// baseline (speedup 1.0000x reference)
#include <cuda_runtime.h>
#include <cuda_bf16.h>
#include <cstdint>

using bf16 = __nv_bfloat16;

static constexpr int B_ = 128, P_ = 196, ENC_ = 2048, A_ = 512, H_ = 512;
static constexpr int V_ = 20000, T_ = 20, H3_ = 1536, EX_ = 2560;
static constexpr long CAP_OFF   = (long)B_ * T_ * V_;   // 51,200,000
static constexpr long ALPHA_OFF = CAP_OFF + B_;         // 51,200,128

// ---------------- device scratch (no allocations allowed) -------------------
__device__ __align__(16) float g_att1[(size_t)B_ * P_ * A_];
__device__ __align__(16) bf16  g_WeT_h[A_ * ENC_], g_WeT_l[A_ * ENC_];
__device__ __align__(16) bf16  g_WdT_h[A_ * H_],   g_WdT_l[A_ * H_];
__device__ __align__(16) bf16  g_Wih_h[H3_ * EX_], g_Wih_l[H3_ * EX_];
__device__ __align__(16) bf16  g_Whh_h[H3_ * H_],  g_Whh_l[H3_ * H_];
__device__ __align__(16) bf16  g_Wo_h[(size_t)V_ * H_], g_Wo_l[(size_t)V_ * H_];
__device__ __align__(16) float g_att2[B_ * A_];
__device__ __align__(16) float g_alpha[B_ * P_];
__device__ __align__(16) float g_x[B_ * EX_];
__device__ __align__(16) float g_gi[B_ * H3_], g_gh[B_ * H3_];
__device__ __align__(16) float g_h[B_ * H_];

// ---------------- helpers ----------------------------------------------------
__device__ __forceinline__ uint32_t s2u(const void* p) {
    return (uint32_t)__cvta_generic_to_shared(p);
}
__device__ __forceinline__ void ldsm4(uint32_t r[4], uint32_t a) {
    asm volatile("ldmatrix.sync.aligned.m8n8.x4.shared.b16 {%0,%1,%2,%3},[%4];"
                 : "=r"(r[0]), "=r"(r[1]), "=r"(r[2]), "=r"(r[3]) : "r"(a));
}
__device__ __forceinline__ void mma16816(float c[4], const uint32_t a[4], const uint32_t b[2]) {
    asm volatile(
        "mma.sync.aligned.m16n8k16.row.col.f32.bf16.bf16.f32 "
        "{%0,%1,%2,%3},{%4,%5,%6,%7},{%8,%9},{%0,%1,%2,%3};"
        : "+f"(c[0]), "+f"(c[1]), "+f"(c[2]), "+f"(c[3])
        : "r"(a[0]), "r"(a[1]), "r"(a[2]), "r"(a[3]), "r"(b[0]), "r"(b[1]));
}

// ---------------- generic split-bf16 GEMM: C[M,N] = A[M,K] * B^T + bias ------
// A: fp32 row-major (lda). B pre-split hi/lo bf16, layout [N,K] row-major (ldb).
// M must be a multiple of 64. N guarded. K must be a multiple of 32.
__global__ __launch_bounds__(128) void gemm_split(
    const float* __restrict__ A, int lda,
    const bf16* __restrict__ Bh, const bf16* __restrict__ Bl, int ldb,
    const float* __restrict__ bias, float* __restrict__ C, long ldc,
    int N, int K)
{
    __shared__ __align__(16) bf16 Ah[64 * 32], Al[64 * 32];
    __shared__ __align__(16) bf16 Bsh[64 * 32], Bsl[64 * 32];
    const int tid = threadIdx.x, lane = tid & 31, warp = tid >> 5;
    const int wm = warp >> 1, wn = warp & 1;
    const int m0 = blockIdx.y * 64, n0 = blockIdx.x * 64;

    float acc[2][4][4];
#pragma unroll
    for (int i = 0; i < 2; i++)
#pragma unroll
        for (int j = 0; j < 4; j++)
#pragma unroll
            for (int k = 0; k < 4; k++) acc[i][j][k] = 0.f;

    for (int k0 = 0; k0 < K; k0 += 32) {
        // load + split A tile 64x32
#pragma unroll
        for (int it = 0; it < 4; it++) {
            int r = (tid >> 3) + it * 16, c4 = (tid & 7) * 4;
            float4 v = *(const float4*)(A + (size_t)(m0 + r) * lda + k0 + c4);
            float vv[4] = {v.x, v.y, v.z, v.w};
#pragma unroll
            for (int j = 0; j < 4; j++) {
                bf16 h = __float2bfloat16(vv[j]);
                Ah[r * 32 + c4 + j] = h;
                Al[r * 32 + c4 + j] = __float2bfloat16(vv[j] - __bfloat162float(h));
            }
        }
        // load B tiles 64x32 (pre-split)
#pragma unroll
        for (int it = 0; it < 8; it++) {
            int idx = tid + it * 128, r = idx >> 4, cu = idx & 15;
            uint32_t uh = 0, ul = 0;
            if (n0 + r < N) {
                size_t base = (size_t)(n0 + r) * ldb + k0;
                uh = *(const uint32_t*)(Bh + base + cu * 2);
                ul = *(const uint32_t*)(Bl + base + cu * 2);
            }
            ((uint32_t*)Bsh)[r * 16 + cu] = uh;
            ((uint32_t*)Bsl)[r * 16 + cu] = ul;
        }
        __syncthreads();
#pragma unroll
        for (int kk = 0; kk < 32; kk += 16) {
            uint32_t ah[2][4], al[2][4], bh[4][2], bl[4][2];
#pragma unroll
            for (int mt = 0; mt < 2; mt++) {
                int off = (wm * 32 + mt * 16 + (lane & 15)) * 32 + kk + ((lane >> 4) << 3);
                ldsm4(ah[mt], s2u(Ah + off));
                ldsm4(al[mt], s2u(Al + off));
            }
#pragma unroll
            for (int np = 0; np < 2; np++) {
                int off = (wn * 32 + np * 16 + (lane & 15)) * 32 + kk + ((lane >> 4) << 3);
                uint32_t t4[4];
                ldsm4(t4, s2u(Bsh + off));
                bh[np * 2][0] = t4[0]; bh[np * 2][1] = t4[2];
                bh[np * 2 + 1][0] = t4[1]; bh[np * 2 + 1][1] = t4[3];
                ldsm4(t4, s2u(Bsl + off));
                bl[np * 2][0] = t4[0]; bl[np * 2][1] = t4[2];
                bl[np * 2 + 1][0] = t4[1]; bl[np * 2 + 1][1] = t4[3];
            }
#pragma unroll
            for (int mt = 0; mt < 2; mt++)
#pragma unroll
                for (int nt = 0; nt < 4; nt++) {
                    mma16816(acc[mt][nt], ah[mt], bh[nt]);
                    mma16816(acc[mt][nt], ah[mt], bl[nt]);
                    mma16816(acc[mt][nt], al[mt], bh[nt]);
                }
        }
        __syncthreads();
    }
    // epilogue
#pragma unroll
    for (int mt = 0; mt < 2; mt++) {
        int row = m0 + wm * 32 + mt * 16 + (lane >> 2);
#pragma unroll
        for (int nt = 0; nt < 4; nt++) {
            int col = n0 + wn * 32 + nt * 8 + (lane & 3) * 2;
            if (col < N) {
                float bb = bias ? bias[col] : 0.f;
                C[(size_t)row * ldc + col] = acc[mt][nt][0] + bb;
                C[(size_t)(row + 8) * ldc + col] = acc[mt][nt][2] + bb;
            }
            if (col + 1 < N) {
                float bb = bias ? bias[col + 1] : 0.f;
                C[(size_t)row * ldc + col + 1] = acc[mt][nt][1] + bb;
                C[(size_t)(row + 8) * ldc + col + 1] = acc[mt][nt][3] + bb;
            }
        }
    }
}

// ---------------- weight prep ------------------------------------------------
__global__ void transpose_split_k(const float* __restrict__ src, bf16* __restrict__ dh,
                                  bf16* __restrict__ dl, int R, int C)
{
    __shared__ float tile[32][33];
    int c0 = blockIdx.x * 32, r0 = blockIdx.y * 32;
    int tx = threadIdx.x, ty = threadIdx.y;  // (32, 8)
#pragma unroll
    for (int i = 0; i < 4; i++) {
        int r = r0 + ty + i * 8;
        if (r < R && c0 + tx < C) tile[ty + i * 8][tx] = src[(size_t)r * C + c0 + tx];
    }
    __syncthreads();
#pragma unroll
    for (int i = 0; i < 4; i++) {
        int orow = c0 + ty + i * 8;  // output row = src col
        int ocol = r0 + tx;          // output col = src row
        if (orow < C && ocol < R) {
            float v = tile[tx][ty + i * 8];
            bf16 h = __float2bfloat16(v);
            dh[(size_t)orow * R + ocol] = h;
            dl[(size_t)orow * R + ocol] = __float2bfloat16(v - __bfloat162float(h));
        }
    }
}

__global__ void split_k(const float* __restrict__ src, bf16* __restrict__ dh,
                        bf16* __restrict__ dl, long n)
{
    long i = (long)blockIdx.x * 256 + threadIdx.x;
    if (i < n) {
        float v = src[i];
        bf16 h = __float2bfloat16(v);
        dh[i] = h;
        dl[i] = __float2bfloat16(v - __bfloat162float(h));
    }
}

// ---------------- per-step fused kernels ------------------------------------
// scores + softmax for one step. One block per batch row.
__global__ void score_softmax_k(const float* __restrict__ wf, const float* __restrict__ bfp,
                                float* __restrict__ out, int t)
{
    __shared__ float att2s[512], wfs[512], sc[196], red[256];
    const int b = blockIdx.x, tid = threadIdx.x, lane = tid & 31, warp = tid >> 5;
    for (int i = tid; i < 512; i += 256) { att2s[i] = g_att2[b * 512 + i]; wfs[i] = wf[i]; }
    __syncthreads();
    const float bfv = bfp[0];
    for (int p = warp; p < 196; p += 8) {
        const float* row = g_att1 + ((size_t)b * 196 + p) * 512;
        float s = 0.f;
#pragma unroll
        for (int i = 0; i < 16; i++) {
            int a = lane + 32 * i;
            float v = row[a] + att2s[a];
            v = v > 0.f ? v : 0.f;
            s += v * wfs[a];
        }
#pragma unroll
        for (int o = 16; o; o >>= 1) s += __shfl_xor_sync(0xffffffffu, s, o);
        if (lane == 0) sc[p] = s + bfv;
    }
    __syncthreads();
    float v = (tid < 196) ? sc[tid] : -1e30f;
    red[tid] = v; __syncthreads();
    for (int o = 128; o; o >>= 1) { if (tid < o) red[tid] = fmaxf(red[tid], red[tid + o]); __syncthreads(); }
    float m = red[0]; __syncthreads();
    float e = (tid < 196) ? __expf(sc[tid] - m) : 0.f;
    red[tid] = e; __syncthreads();
    for (int o = 128; o; o >>= 1) { if (tid < o) red[tid] += red[tid + o]; __syncthreads(); }
    float inv = 1.f / red[0];
    if (tid < 196) {
        float a = e * inv;
        g_alpha[b * 196 + tid] = a;
        out[ALPHA_OFF + ((size_t)b * 20 + t) * 196 + tid] = a;
    }
}

// ctx[b][e] = sum_p alpha[b][p] * img[b][p][e]  -> g_x[b][512 + e]
__global__ void ctx_k(const float* __restrict__ img)
{
    __shared__ float al[196];
    const int b = blockIdx.y, e = blockIdx.x * 128 + threadIdx.x;
    for (int i = threadIdx.x; i < 196; i += 128) al[i] = g_alpha[b * 196 + i];
    __syncthreads();
    const float* ip = img + (size_t)b * 196 * 2048 + e;
    float acc = 0.f;
#pragma unroll 4
    for (int p = 0; p < 196; p++) acc += al[p] * ip[(size_t)p * 2048];
    g_x[b * 2560 + 512 + e] = acc;
}

__global__ void gather_emb_k(const float* __restrict__ emb, const int* __restrict__ cap, int t)
{
    const int b = blockIdx.x;
    const int w = cap[b * 20 + t - 1];
    for (int i = threadIdx.x; i < 512; i += 128) g_x[b * 2560 + i] = emb[(size_t)w * 512 + i];
}

__global__ void gates_k()
{
    int idx = blockIdx.x * 256 + threadIdx.x;
    if (idx >= 128 * 512) return;
    int b = idx >> 9, j = idx & 511;
    const float* gi = g_gi + b * 1536;
    const float* gh = g_gh + b * 1536;
    float r = 1.f / (1.f + __expf(-(gi[j] + gh[j])));
    float z = 1.f / (1.f + __expf(-(gi[512 + j] + gh[512 + j])));
    float n = tanhf(gi[1024 + j] + r * gh[1024 + j]);
    float h = g_h[idx];
    g_h[idx] = (1.f - z) * n + z * h;
}

__global__ void zero_h_k()
{
    int i = blockIdx.x * 256 + threadIdx.x;
    if (i < 128 * 512) g_h[i] = 0.f;
}

// zero predictions[:,0,:] (with [b][1]=1), zero alphas[:,0,:], write caplen as float
__global__ void init_out_k(float* __restrict__ out, const int* __restrict__ caplen)
{
    long i = (long)blockIdx.x * 256 + threadIdx.x;
    const long n0 = (long)128 * 20000;
    if (i < n0) {
        long b = i / 20000, v2 = i % 20000;
        out[b * 400000 + v2] = (v2 == 1) ? 1.f : 0.f;
    } else if (i < n0 + 128 * 196) {
        long j = i - n0;
        long b = j / 196, p = j % 196;
        out[ALPHA_OFF + b * (20 * 196) + p] = 0.f;
    } else if (i < n0 + 128 * 196 + 128) {
        int b = (int)(i - n0 - 128 * 196);
        out[CAP_OFF + b] = (float)caplen[b];
    }
}

// ---------------- host side --------------------------------------------------
extern "C" void kernel_launch(void* const* d_in, const int* in_sizes, int n_in,
                              void* d_out, int out_size)
{
    const float* img  = (const float*)d_in[0];
    const int*   cap  = (const int*)d_in[1];
    const int*   cpl  = (const int*)d_in[2];
    const float* emb  = (const float*)d_in[3];
    const float* We   = (const float*)d_in[4];
    const float* be   = (const float*)d_in[5];
    const float* Wd   = (const float*)d_in[6];
    const float* bd   = (const float*)d_in[7];
    const float* Wf   = (const float*)d_in[8];
    const float* bfp  = (const float*)d_in[9];
    const float* Wih  = (const float*)d_in[10];
    const float* bih  = (const float*)d_in[11];
    const float* Whh  = (const float*)d_in[12];
    const float* bhh  = (const float*)d_in[13];
    const float* Wo   = (const float*)d_in[14];
    const float* bo   = (const float*)d_in[15];
    float* out = (float*)d_out;

    void *pWeTh, *pWeTl, *pWdTh, *pWdTl, *pWihh, *pWihl, *pWhhh, *pWhhl, *pWoh, *pWol;
    void *pAtt1, *pAtt2, *pH, *pX, *pGi, *pGh;
    cudaGetSymbolAddress(&pWeTh, g_WeT_h); cudaGetSymbolAddress(&pWeTl, g_WeT_l);
    cudaGetSymbolAddress(&pWdTh, g_WdT_h); cudaGetSymbolAddress(&pWdTl, g_WdT_l);
    cudaGetSymbolAddress(&pWihh, g_Wih_h); cudaGetSymbolAddress(&pWihl, g_Wih_l);
    cudaGetSymbolAddress(&pWhhh, g_Whh_h); cudaGetSymbolAddress(&pWhhl, g_Whh_l);
    cudaGetSymbolAddress(&pWoh,  g_Wo_h);  cudaGetSymbolAddress(&pWol,  g_Wo_l);
    cudaGetSymbolAddress(&pAtt1, g_att1);  cudaGetSymbolAddress(&pAtt2, g_att2);
    cudaGetSymbolAddress(&pH, g_h); cudaGetSymbolAddress(&pX, g_x);
    cudaGetSymbolAddress(&pGi, g_gi); cudaGetSymbolAddress(&pGh, g_gh);

    // weight prep (per launch; deterministic)
    transpose_split_k<<<dim3(16, 64), dim3(32, 8)>>>(We, (bf16*)pWeTh, (bf16*)pWeTl, 2048, 512);
    transpose_split_k<<<dim3(16, 16), dim3(32, 8)>>>(Wd, (bf16*)pWdTh, (bf16*)pWdTl, 512, 512);
    split_k<<<(int)(((long)1536 * 2560 + 255) / 256), 256>>>(Wih, (bf16*)pWihh, (bf16*)pWihl, (long)1536 * 2560);
    split_k<<<(int)(((long)1536 * 512 + 255) / 256), 256>>>(Whh, (bf16*)pWhhh, (bf16*)pWhhl, (long)1536 * 512);
    split_k<<<(int)(((long)20000 * 512 + 255) / 256), 256>>>(Wo, (bf16*)pWoh, (bf16*)pWol, (long)20000 * 512);
    zero_h_k<<<256, 256>>>();
    {
        long tot = (long)128 * 20000 + 128 * 196 + 128;
        init_out_k<<<(int)((tot + 255) / 256), 256>>>(out, cpl);
    }
    // att1 = img @ We + be  -> [25088, 512] fp32
    gemm_split<<<dim3(8, 392), 128>>>(img, 2048, (bf16*)pWeTh, (bf16*)pWeTl, 2048,
                                      be, (float*)pAtt1, 512, 512, 2048);

    for (int t = 1; t < 20; t++) {
        // att2 = h @ Wd + bd
        gemm_split<<<dim3(8, 2), 128>>>((const float*)pH, 512, (bf16*)pWdTh, (bf16*)pWdTl, 512,
                                        bd, (float*)pAtt2, 512, 512, 512);
        score_softmax_k<<<128, 256>>>(Wf, bfp, out, t);
        gather_emb_k<<<128, 128>>>(emb, cap, t);
        ctx_k<<<dim3(16, 128), 128>>>(img);
        // gi = x @ W_ih^T + b_ih
        gemm_split<<<dim3(24, 2), 128>>>((const float*)pX, 2560, (bf16*)pWihh, (bf16*)pWihl, 2560,
                                         bih, (float*)pGi, 1536, 1536, 2560);
        // gh = h @ W_hh^T + b_hh
        gemm_split<<<dim3(24, 2), 128>>>((const float*)pH, 512, (bf16*)pWhhh, (bf16*)pWhhl, 512,
                                         bhh, (float*)pGh, 1536, 1536, 512);
        gates_k<<<256, 256>>>();
        // preds = h_new @ Wo^T + bo  -> predictions[:, t, :]
        gemm_split<<<dim3(313, 2), 128>>>((const float*)pH, 512, (bf16*)pWoh, (bf16*)pWol, 512,
                                          bo, out + (long)t * 20000, 400000, 20000, 512);
    }
    (void)in_sizes; (void)n_in; (void)out_size;
}

// round 3
// speedup vs baseline: 2.5188x; 2.5188x over previous
#include <cuda_runtime.h>
#include <cuda_bf16.h>
#include <cstdint>

using bf16 = __nv_bfloat16;

static constexpr int B_ = 128, P_ = 196, ENC_ = 2048, A_ = 512, H_ = 512;
static constexpr int V_ = 20000, T_ = 20, H3_ = 1536, EX_ = 2560;
static constexpr long CAP_OFF   = (long)B_ * T_ * V_;   // 51,200,000
static constexpr long ALPHA_OFF = CAP_OFF + B_;         // 51,200,128
static constexpr int  M1_ = B_ * P_;                    // 25088
static constexpr int  MH_ = (T_ - 1) * B_;              // 2432

// ---------------- device scratch ------------------------------------------
__device__ __align__(16) bf16  g_img_h[(size_t)M1_ * ENC_], g_img_l[(size_t)M1_ * ENC_];
__device__ __align__(16) float g_att1[(size_t)M1_ * A_];
__device__ __align__(16) bf16  g_WeT_h[A_ * ENC_], g_WeT_l[A_ * ENC_];
__device__ __align__(16) bf16  g_Bcat_h[2048 * 512], g_Bcat_l[2048 * 512];
__device__ __align__(16) float g_bias_cat[2048];
__device__ __align__(16) bf16  g_Wih_h[H3_ * EX_], g_Wih_l[H3_ * EX_];
__device__ __align__(16) bf16  g_Wo_h[(size_t)V_ * H_], g_Wo_l[(size_t)V_ * H_];
__device__ __align__(16) float g_ag[2][B_ * 2048];     // split-K partials: att2|gh
__device__ __align__(16) float g_gi4[4][B_ * H3_];     // split-K partials: gi
__device__ __align__(16) float g_alpha[B_ * P_];
__device__ __align__(16) bf16  g_x_h[B_ * EX_], g_x_l[B_ * EX_];
__device__ __align__(16) float g_h[B_ * H_];
__device__ __align__(16) bf16  g_h_h[B_ * H_], g_h_l[B_ * H_];
__device__ __align__(16) bf16  g_hall_h[MH_ * H_], g_hall_l[MH_ * H_];

// ---------------- helpers --------------------------------------------------
__device__ __forceinline__ uint32_t s2u(const void* p) {
    return (uint32_t)__cvta_generic_to_shared(p);
}
__device__ __forceinline__ void ldsm4(uint32_t r[4], uint32_t a) {
    asm volatile("ldmatrix.sync.aligned.m8n8.x4.shared.b16 {%0,%1,%2,%3},[%4];"
                 : "=r"(r[0]), "=r"(r[1]), "=r"(r[2]), "=r"(r[3]) : "r"(a));
}
__device__ __forceinline__ void mma16816(float c[4], const uint32_t a[4], const uint32_t b[2]) {
    asm volatile(
        "mma.sync.aligned.m16n8k16.row.col.f32.bf16.bf16.f32 "
        "{%0,%1,%2,%3},{%4,%5,%6,%7},{%8,%9},{%0,%1,%2,%3};"
        : "+f"(c[0]), "+f"(c[1]), "+f"(c[2]), "+f"(c[3])
        : "r"(a[0]), "r"(a[1]), "r"(a[2]), "r"(a[3]), "r"(b[0]), "r"(b[1]));
}
#define CP16(d, s) asm volatile("cp.async.cg.shared.global [%0],[%1],16;\n" :: "r"(d), "l"(s))
#define CPCOMMIT() asm volatile("cp.async.commit_group;\n")

__device__ __forceinline__ void split2(float v, bf16& h, bf16& l) {
    h = __float2bfloat16(v);
    l = __float2bfloat16(v - __bfloat162float(h));
}

// ---------------- main GEMM: C = A(split) @ B(split)^T (+bias) --------------
// A [M,K] row-major hi/lo bf16. B [N,K] row-major hi/lo bf16.
// CTA 256 thr, tile 128(M) x 64(N) x 32(K), cp.async double-buffered.
// blockIdx.z = split-K index (Ksub = Ktot/gridDim.z); partial -> C + z*part_stride.
// Row address: C + by*tile_stride + z*part_stride + r_local*row_stride + col.
// Smem rows padded to 40 bf16 (80B) -> conflict-free ldmatrix.
static constexpr int SA = 128 * 40;   // 5120
static constexpr int SB = 64 * 40;    // 2560
static constexpr int STG = 2 * SA + 2 * SB;  // 15360 elems per stage
static constexpr int GEMM_SMEM = 2 * STG * 2; // bytes = 61440

__global__ __launch_bounds__(256) void gemm2(
    const bf16* __restrict__ Agh, const bf16* __restrict__ Agl, int lda,
    const bf16* __restrict__ Bgh, const bf16* __restrict__ Bgl, int ldb,
    const float* __restrict__ bias, float* __restrict__ Cbase,
    long tile_stride, long row_stride, long part_stride,
    int N, int Ktot)
{
    extern __shared__ __align__(16) bf16 sm[];
    const int tid = threadIdx.x, lane = tid & 31, warp = tid >> 5;
    const int wm = warp >> 1, wn = warp & 1;
    const int n0 = blockIdx.x * 64, m0 = blockIdx.y * 128;
    const int ks = blockIdx.z;
    const int Ksub = Ktot / gridDim.z, kbase = ks * Ksub;

    float acc[2][4][4];
#pragma unroll
    for (int i = 0; i < 2; i++)
#pragma unroll
        for (int j = 0; j < 4; j++)
#pragma unroll
            for (int k = 0; k < 4; k++) acc[i][j][k] = 0.f;

    auto load_stage = [&](int st, int k0) {
        bf16* As_h = sm + st * STG;
        bf16* As_l = As_h + SA;
        bf16* Bs_h = As_l + SA;
        bf16* Bs_l = Bs_h + SB;
#pragma unroll
        for (int it = 0; it < 2; it++) {
            int idx = tid + it * 256, r = idx >> 2, ch = idx & 3;
            size_t go = (size_t)(m0 + r) * lda + k0 + ch * 8;
            CP16(s2u(As_h + r * 40 + ch * 8), Agh + go);
            CP16(s2u(As_l + r * 40 + ch * 8), Agl + go);
        }
        {
            int r = tid >> 2, ch = tid & 3;
            int rr = (n0 + r < N) ? (n0 + r) : (N - 1);
            size_t go = (size_t)rr * ldb + k0 + ch * 8;
            CP16(s2u(Bs_h + r * 40 + ch * 8), Bgh + go);
            CP16(s2u(Bs_l + r * 40 + ch * 8), Bgl + go);
        }
        CPCOMMIT();
    };

    const int nk = Ksub / 32;
    load_stage(0, kbase);
    for (int i = 0; i < nk; i++) {
        if (i + 1 < nk) {
            load_stage((i + 1) & 1, kbase + (i + 1) * 32);
            asm volatile("cp.async.wait_group 1;\n");
        } else {
            asm volatile("cp.async.wait_group 0;\n");
        }
        __syncthreads();
        bf16* As_h = sm + (i & 1) * STG;
        bf16* As_l = As_h + SA;
        bf16* Bs_h = As_l + SA;
        bf16* Bs_l = Bs_h + SB;
#pragma unroll
        for (int kk = 0; kk < 32; kk += 16) {
            uint32_t ah[2][4], al[2][4], bh[4][2], bl[4][2];
#pragma unroll
            for (int mt = 0; mt < 2; mt++) {
                int off = (wm * 32 + mt * 16 + (lane & 15)) * 40 + kk + ((lane >> 4) << 3);
                ldsm4(ah[mt], s2u(As_h + off));
                ldsm4(al[mt], s2u(As_l + off));
            }
#pragma unroll
            for (int ng = 0; ng < 2; ng++) {
                int off = (wn * 32 + ng * 16 + (lane & 15)) * 40 + kk + ((lane >> 4) << 3);
                uint32_t t4[4];
                ldsm4(t4, s2u(Bs_h + off));
                bh[ng * 2][0] = t4[0]; bh[ng * 2][1] = t4[2];
                bh[ng * 2 + 1][0] = t4[1]; bh[ng * 2 + 1][1] = t4[3];
                ldsm4(t4, s2u(Bs_l + off));
                bl[ng * 2][0] = t4[0]; bl[ng * 2][1] = t4[2];
                bl[ng * 2 + 1][0] = t4[1]; bl[ng * 2 + 1][1] = t4[3];
            }
#pragma unroll
            for (int mt = 0; mt < 2; mt++)
#pragma unroll
                for (int nt = 0; nt < 4; nt++) {
                    mma16816(acc[mt][nt], ah[mt], bh[nt]);
                    mma16816(acc[mt][nt], ah[mt], bl[nt]);
                    mma16816(acc[mt][nt], al[mt], bh[nt]);
                }
        }
        __syncthreads();
    }

    float* Cp = Cbase + (long)blockIdx.y * tile_stride + (long)ks * part_stride;
    const bool addb = (bias != nullptr) && (ks == 0);
#pragma unroll
    for (int mt = 0; mt < 2; mt++) {
        int r = wm * 32 + mt * 16 + (lane >> 2);
#pragma unroll
        for (int nt = 0; nt < 4; nt++) {
            int col = n0 + wn * 32 + nt * 8 + (lane & 3) * 2;
            if (col < N) {
                float bb = addb ? bias[col] : 0.f;
                Cp[(long)r * row_stride + col]       = acc[mt][nt][0] + bb;
                Cp[(long)(r + 8) * row_stride + col] = acc[mt][nt][2] + bb;
            }
            if (col + 1 < N) {
                float bb = addb ? bias[col + 1] : 0.f;
                Cp[(long)r * row_stride + col + 1]       = acc[mt][nt][1] + bb;
                Cp[(long)(r + 8) * row_stride + col + 1] = acc[mt][nt][3] + bb;
            }
        }
    }
}

// ---------------- prep kernels ----------------------------------------------
__global__ void split4_k(const float* __restrict__ src, bf16* __restrict__ dh,
                         bf16* __restrict__ dl, long n4)
{
    long i = (long)blockIdx.x * 256 + threadIdx.x;
    if (i >= n4) return;
    float4 v = ((const float4*)src)[i];
    bf16 h0, h1, h2, h3, l0, l1, l2, l3;
    split2(v.x, h0, l0); split2(v.y, h1, l1); split2(v.z, h2, l2); split2(v.w, h3, l3);
    ((__nv_bfloat162*)(dh + 4 * i))[0] = {h0, h1};
    ((__nv_bfloat162*)(dh + 4 * i))[1] = {h2, h3};
    ((__nv_bfloat162*)(dl + 4 * i))[0] = {l0, l1};
    ((__nv_bfloat162*)(dl + 4 * i))[1] = {l2, l3};
}

__global__ void transpose_split_k(const float* __restrict__ src, bf16* __restrict__ dh,
                                  bf16* __restrict__ dl, int R, int C)
{
    __shared__ float tile[32][33];
    int c0 = blockIdx.x * 32, r0 = blockIdx.y * 32;
    int tx = threadIdx.x, ty = threadIdx.y;  // (32, 8)
#pragma unroll
    for (int i = 0; i < 4; i++) {
        int r = r0 + ty + i * 8;
        if (r < R && c0 + tx < C) tile[ty + i * 8][tx] = src[(size_t)r * C + c0 + tx];
    }
    __syncthreads();
#pragma unroll
    for (int i = 0; i < 4; i++) {
        int orow = c0 + ty + i * 8, ocol = r0 + tx;
        if (orow < C && ocol < R) {
            bf16 h, l;
            split2(tile[tx][ty + i * 8], h, l);
            dh[(size_t)orow * R + ocol] = h;
            dl[(size_t)orow * R + ocol] = l;
        }
    }
}

__global__ void biascat_k(const float* __restrict__ bd, const float* __restrict__ bhh)
{
    int i = blockIdx.x * 256 + threadIdx.x;
    if (i < 512) g_bias_cat[i] = bd[i];
    else if (i < 2048) g_bias_cat[i] = bhh[i - 512];
}

__global__ void zero_h_k()
{
    int i = blockIdx.x * 256 + threadIdx.x;
    if (i < B_ * H_) { g_h[i] = 0.f; g_h_h[i] = __float2bfloat16(0.f); g_h_l[i] = __float2bfloat16(0.f); }
}

__global__ void init_out_k(float* __restrict__ out, const int* __restrict__ caplen)
{
    long i = (long)blockIdx.x * 256 + threadIdx.x;
    const long n0 = (long)B_ * V_;
    if (i < n0) {
        long b = i / V_, v2 = i % V_;
        out[b * 400000 + v2] = (v2 == 1) ? 1.f : 0.f;
    } else if (i < n0 + B_ * P_) {
        long j = i - n0, b = j / P_, p = j % P_;
        out[ALPHA_OFF + b * (T_ * P_) + p] = 0.f;
    } else if (i < n0 + B_ * P_ + B_) {
        int b = (int)(i - n0 - B_ * P_);
        out[CAP_OFF + b] = (float)caplen[b];
    }
}

// ---------------- per-step kernels ------------------------------------------
__global__ void score_softmax_k(const float* __restrict__ wf, const float* __restrict__ bfp,
                                float* __restrict__ out, int t)
{
    __shared__ float att2s[512], wfs[512], sc[256], red[256];
    const int b = blockIdx.x, tid = threadIdx.x, lane = tid & 31, warp = tid >> 5;
    for (int i = tid; i < 512; i += 256) {
        att2s[i] = g_ag[0][b * 2048 + i] + g_ag[1][b * 2048 + i];
        wfs[i] = wf[i];
    }
    __syncthreads();
    const float bfv = bfp[0];
    for (int p = warp; p < 196; p += 8) {
        const float4* row = (const float4*)(g_att1 + ((size_t)b * 196 + p) * 512);
        float s = 0.f;
#pragma unroll
        for (int i = 0; i < 4; i++) {
            int c = lane + i * 32;
            float4 v = row[c];
            float4 a = ((const float4*)att2s)[c];
            float4 w = ((const float4*)wfs)[c];
            s += fmaxf(v.x + a.x, 0.f) * w.x + fmaxf(v.y + a.y, 0.f) * w.y
               + fmaxf(v.z + a.z, 0.f) * w.z + fmaxf(v.w + a.w, 0.f) * w.w;
        }
#pragma unroll
        for (int o = 16; o; o >>= 1) s += __shfl_xor_sync(0xffffffffu, s, o);
        if (lane == 0) sc[p] = s + bfv;
    }
    __syncthreads();
    float v = (tid < 196) ? sc[tid] : -1e30f;
    red[tid] = v; __syncthreads();
    for (int o = 128; o; o >>= 1) { if (tid < o) red[tid] = fmaxf(red[tid], red[tid + o]); __syncthreads(); }
    float m = red[0]; __syncthreads();
    float e = (tid < 196) ? __expf(sc[tid] - m) : 0.f;
    red[tid] = e; __syncthreads();
    for (int o = 128; o; o >>= 1) { if (tid < o) red[tid] += red[tid + o]; __syncthreads(); }
    float inv = 1.f / red[0];
    if (tid < 196) {
        float a = e * inv;
        g_alpha[b * 196 + tid] = a;
        out[ALPHA_OFF + ((size_t)b * 20 + t) * 196 + tid] = a;
    }
}

// ctx weighted sum (writes split x ctx-part) + embedding gather (block x==0)
__global__ void ctx_k(const float* __restrict__ img, const float* __restrict__ emb,
                      const int* __restrict__ cap, int t)
{
    __shared__ float al[196];
    const int b = blockIdx.y, tid = threadIdx.x;
    for (int i = tid; i < 196; i += 128) al[i] = g_alpha[b * 196 + i];
    __syncthreads();
    const int c4 = blockIdx.x * 128 + tid;  // 0..511 float4 columns
    const float4* ip = (const float4*)(img + (size_t)b * 196 * 2048) + c4;
    float4 acc = {0.f, 0.f, 0.f, 0.f};
#pragma unroll 4
    for (int p = 0; p < 196; p++) {
        float4 v = ip[(size_t)p * 512];
        float a = al[p];
        acc.x += a * v.x; acc.y += a * v.y; acc.z += a * v.z; acc.w += a * v.w;
    }
    int o = b * 2560 + 512 + c4 * 4;
    bf16 h0, h1, h2, h3, l0, l1, l2, l3;
    split2(acc.x, h0, l0); split2(acc.y, h1, l1); split2(acc.z, h2, l2); split2(acc.w, h3, l3);
    ((__nv_bfloat162*)(g_x_h + o))[0] = {h0, h1};
    ((__nv_bfloat162*)(g_x_h + o))[1] = {h2, h3};
    ((__nv_bfloat162*)(g_x_l + o))[0] = {l0, l1};
    ((__nv_bfloat162*)(g_x_l + o))[1] = {l2, l3};
    if (blockIdx.x == 0) {
        int w = cap[b * 20 + t - 1];
        for (int i = tid; i < 512; i += 128) {
            bf16 h, l;
            split2(emb[(size_t)w * 512 + i], h, l);
            g_x_h[b * 2560 + i] = h;
            g_x_l[b * 2560 + i] = l;
        }
    }
}

__global__ void gates_k(int t)
{
    int idx = blockIdx.x * 256 + threadIdx.x;
    if (idx >= B_ * H_) return;
    int b = idx >> 9, j = idx & 511;
    int base = b * 1536;
    float gir = 0.f, giz = 0.f, gin = 0.f;
#pragma unroll
    for (int s = 0; s < 4; s++) {
        gir += g_gi4[s][base + j];
        giz += g_gi4[s][base + 512 + j];
        gin += g_gi4[s][base + 1024 + j];
    }
    int gb = b * 2048;
    float ghr = g_ag[0][gb + 512 + j]  + g_ag[1][gb + 512 + j];
    float ghz = g_ag[0][gb + 1024 + j] + g_ag[1][gb + 1024 + j];
    float ghn = g_ag[0][gb + 1536 + j] + g_ag[1][gb + 1536 + j];
    float r = 1.f / (1.f + __expf(-(gir + ghr)));
    float z = 1.f / (1.f + __expf(-(giz + ghz)));
    float n = tanhf(gin + r * ghn);
    float h = g_h[idx];
    float hn = (1.f - z) * n + z * h;
    g_h[idx] = hn;
    bf16 hh, hl;
    split2(hn, hh, hl);
    g_h_h[idx] = hh; g_h_l[idx] = hl;
    int ro = (t - 1) * (B_ * H_) + idx;
    g_hall_h[ro] = hh; g_hall_l[ro] = hl;
}

// ---------------- host -------------------------------------------------------
extern "C" void kernel_launch(void* const* d_in, const int* in_sizes, int n_in,
                              void* d_out, int out_size)
{
    const float* img = (const float*)d_in[0];
    const int*   cap = (const int*)d_in[1];
    const int*   cpl = (const int*)d_in[2];
    const float* emb = (const float*)d_in[3];
    const float* We  = (const float*)d_in[4];
    const float* be  = (const float*)d_in[5];
    const float* Wd  = (const float*)d_in[6];
    const float* bd  = (const float*)d_in[7];
    const float* Wf  = (const float*)d_in[8];
    const float* bfp = (const float*)d_in[9];
    const float* Wih = (const float*)d_in[10];
    const float* bih = (const float*)d_in[11];
    const float* Whh = (const float*)d_in[12];
    const float* bhh = (const float*)d_in[13];
    const float* Wo  = (const float*)d_in[14];
    const float* bo  = (const float*)d_in[15];
    float* out = (float*)d_out;

    static bool attr_set = false;
    if (!attr_set) {
        cudaFuncSetAttribute(gemm2, cudaFuncAttributeMaxDynamicSharedMemorySize, GEMM_SMEM);
        attr_set = true;
    }

    void *pImgH, *pImgL, *pAtt1, *pWeTh, *pWeTl, *pBch, *pBcl, *pBias;
    void *pWihh, *pWihl, *pWoh, *pWol, *pAg, *pGi4, *pXh, *pXl, *pHh, *pHl, *pHaH, *pHaL;
    cudaGetSymbolAddress(&pImgH, g_img_h); cudaGetSymbolAddress(&pImgL, g_img_l);
    cudaGetSymbolAddress(&pAtt1, g_att1);
    cudaGetSymbolAddress(&pWeTh, g_WeT_h); cudaGetSymbolAddress(&pWeTl, g_WeT_l);
    cudaGetSymbolAddress(&pBch, g_Bcat_h); cudaGetSymbolAddress(&pBcl, g_Bcat_l);
    cudaGetSymbolAddress(&pBias, g_bias_cat);
    cudaGetSymbolAddress(&pWihh, g_Wih_h); cudaGetSymbolAddress(&pWihl, g_Wih_l);
    cudaGetSymbolAddress(&pWoh, g_Wo_h);   cudaGetSymbolAddress(&pWol, g_Wo_l);
    cudaGetSymbolAddress(&pAg, g_ag);      cudaGetSymbolAddress(&pGi4, g_gi4);
    cudaGetSymbolAddress(&pXh, g_x_h);     cudaGetSymbolAddress(&pXl, g_x_l);
    cudaGetSymbolAddress(&pHh, g_h_h);     cudaGetSymbolAddress(&pHl, g_h_l);
    cudaGetSymbolAddress(&pHaH, g_hall_h); cudaGetSymbolAddress(&pHaL, g_hall_l);

    // ---- prep ----
    {
        long n4 = (long)M1_ * ENC_ / 4;
        split4_k<<<(int)((n4 + 255) / 256), 256>>>(img, (bf16*)pImgH, (bf16*)pImgL, n4);
    }
    transpose_split_k<<<dim3(16, 64), dim3(32, 8)>>>(We, (bf16*)pWeTh, (bf16*)pWeTl, 2048, 512);
    transpose_split_k<<<dim3(16, 16), dim3(32, 8)>>>(Wd, (bf16*)pBch, (bf16*)pBcl, 512, 512);
    {
        long n4 = (long)H3_ * H_ / 4;
        split4_k<<<(int)((n4 + 255) / 256), 256>>>(Whh, (bf16*)pBch + 512 * 512, (bf16*)pBcl + 512 * 512, n4);
    }
    {
        long n4 = (long)H3_ * EX_ / 4;
        split4_k<<<(int)((n4 + 255) / 256), 256>>>(Wih, (bf16*)pWihh, (bf16*)pWihl, n4);
    }
    {
        long n4 = (long)V_ * H_ / 4;
        split4_k<<<(int)((n4 + 255) / 256), 256>>>(Wo, (bf16*)pWoh, (bf16*)pWol, n4);
    }
    biascat_k<<<8, 256>>>(bd, bhh);
    zero_h_k<<<256, 256>>>();
    {
        long tot = (long)B_ * V_ + B_ * P_ + B_;
        init_out_k<<<(int)((tot + 255) / 256), 256>>>(out, cpl);
    }

    // att1 = img @ We^T + be -> [25088, 512]
    gemm2<<<dim3(8, 196, 1), 256, GEMM_SMEM>>>(
        (bf16*)pImgH, (bf16*)pImgL, 2048, (bf16*)pWeTh, (bf16*)pWeTl, 2048,
        be, (float*)pAtt1, (long)128 * 512, 512, 0, 512, 2048);

    for (int t = 1; t < 20; t++) {
        // [att2 | gh] = h @ Bcat^T (+biascat), split-K=2 -> g_ag[0],g_ag[1]
        gemm2<<<dim3(32, 1, 2), 256, GEMM_SMEM>>>(
            (bf16*)pHh, (bf16*)pHl, 512, (bf16*)pBch, (bf16*)pBcl, 512,
            (const float*)pBias, (float*)pAg, 0, 2048, (long)B_ * 2048, 2048, 512);
        score_softmax_k<<<128, 256>>>(Wf, bfp, out, t);
        ctx_k<<<dim3(4, 128), 128>>>(img, emb, cap, t);
        // gi = x @ Wih^T (+bih), split-K=4 -> g_gi4[0..3]
        gemm2<<<dim3(24, 1, 4), 256, GEMM_SMEM>>>(
            (bf16*)pXh, (bf16*)pXl, 2560, (bf16*)pWihh, (bf16*)pWihl, 2560,
            bih, (float*)pGi4, 0, 1536, (long)B_ * 1536, 1536, 2560);
        gates_k<<<256, 256>>>(t);
    }

    // preds (batched over all steps): [2432, 20000] -> out[b*400000 + t*20000 + v]
    gemm2<<<dim3(313, 19, 1), 256, GEMM_SMEM>>>(
        (bf16*)pHaH, (bf16*)pHaL, 512, (bf16*)pWoh, (bf16*)pWol, 512,
        bo, out + 20000, 20000, 400000, 0, 20000, 512);

    (void)in_sizes; (void)n_in; (void)out_size;
}